// round 9
// baseline (speedup 1.0000x reference)
#include <cuda_runtime.h>

#define FULLMASK 0xffffffffu
#define MAXN 16384

typedef unsigned long long u64;

// Scratch (device globals — no allocation)
__device__ float g_G[MAXN * 128];   // G[j][tm] = x_j . tf_{t,m}
__device__ float g_xn2[MAXN];       // |x_j|^2
__device__ float g_tf2[128];        // |tf_{t,m}|^2
__device__ float g_C2s[128 * 8];    // symmetrized C2 rows

// ---------------- native u64-packed f32x2 helpers ----------------
__device__ __forceinline__ u64 fma2u(u64 a, u64 b, u64 c) {
    u64 d; asm("fma.rn.f32x2 %0,%1,%2,%3;" : "=l"(d) : "l"(a), "l"(b), "l"(c)); return d;
}
__device__ __forceinline__ u64 mul2u(u64 a, u64 b) {
    u64 d; asm("mul.rn.f32x2 %0,%1,%2;" : "=l"(d) : "l"(a), "l"(b)); return d;
}
__device__ __forceinline__ u64 add2u(u64 a, u64 b) {
    u64 d; asm("add.rn.f32x2 %0,%1,%2;" : "=l"(d) : "l"(a), "l"(b)); return d;
}
__device__ __forceinline__ u64 pack2(float x, float y) {
    u64 d; asm("mov.b64 %0,{%1,%2};" : "=l"(d) : "f"(x), "f"(y)); return d;
}
__device__ __forceinline__ void unpack2(u64 v, float& x, float& y) {
    asm("mov.b64 {%0,%1},%2;" : "=f"(x), "=f"(y) : "l"(v));
}
__device__ __forceinline__ float ex2(float x) {
    float r; asm("ex2.approx.f32 %0, %1;" : "=f"(r) : "f"(x)); return r;
}
__device__ __forceinline__ float rcpf(float x) {
    float r; asm("rcp.approx.f32 %0, %1;" : "=f"(r) : "f"(x)); return r;
}

// ---------------- Kernel A: precompute (32 nodes/block) ----------------
__global__ void __launch_bounds__(128)
precompute_kernel(const float* __restrict__ x,
                  const float* __restrict__ lt,
                  const float* __restrict__ tf,
                  int N)
{
    __shared__ float xs[32][128];
    const int tid = threadIdx.x;
    const int n0  = blockIdx.x * 32;

    #pragma unroll
    for (int j = 0; j < 32; j++)
        xs[j][tid] = (n0 + j < N) ? __ldg(&x[(n0 + j) * 128 + tid]) : 0.f;
    __syncthreads();

    const float4* tfr = (const float4*)(tf + tid * 128);
    float acc[32];
    #pragma unroll
    for (int j = 0; j < 32; j++) acc[j] = 0.f;
    float tf2a = 0.f;
    #pragma unroll 1
    for (int c4 = 0; c4 < 32; c4++) {
        float4 tv = __ldg(&tfr[c4]);
        tf2a += tv.x*tv.x + tv.y*tv.y + tv.z*tv.z + tv.w*tv.w;
        #pragma unroll
        for (int j = 0; j < 32; j++) {
            float4 v = *(const float4*)&xs[j][c4 * 4];
            acc[j] += v.x*tv.x + v.y*tv.y + v.z*tv.z + v.w*tv.w;
        }
    }
    #pragma unroll
    for (int j = 0; j < 32; j++)
        if (n0 + j < N) g_G[(n0 + j) * 128 + tid] = acc[j];

    const int jn = tid >> 2, off = (tid & 3) * 32;
    float s = 0.f;
    #pragma unroll
    for (int k = 0; k < 32; k++) { float v = xs[jn][off + k]; s += v * v; }
    s += __shfl_xor_sync(FULLMASK, s, 1);
    s += __shfl_xor_sync(FULLMASK, s, 2);
    if ((tid & 3) == 0 && n0 + jn < N) g_xn2[n0 + jn] = s;

    if (blockIdx.x == 0) {
        g_tf2[tid] = tf2a;
        const int t = tid >> 3, m = tid & 7;
        #pragma unroll
        for (int l = 0; l < 8; l++)
            g_C2s[tid * 8 + l] = 0.5f * (__ldg(&lt[(t * 8 + m) * 8 + l]) +
                                         __ldg(&lt[(t * 8 + l) * 8 + m]));
    }
}

// +EKC*A for the star graph, 2-lane groups. K holds P (u64-packed).
__device__ __forceinline__ void compute_pA(
    const u64 K[9][4], const u64 (*C2p)[64], int tid,
    int l, int mate_src,
    u64 pA0f[4], u64 pArf[4])
{
    u64 s2[4], p02[4];
    #pragma unroll
    for (int c = 0; c < 4; c++) {
        u64 a = (l == 0) ? 0ull : K[0][c];
        u64 b = add2u(K[1][c], K[2][c]);
        a = add2u(a, add2u(K[3][c], K[4][c]));
        b = add2u(b, add2u(K[5][c], K[6][c]));
        a = add2u(a, add2u(K[7][c], K[8][c]));
        a = add2u(a, b);
        float ax, ay; unpack2(a, ax, ay);
        ax += __shfl_xor_sync(FULLMASK, ax, 1);
        ay += __shfl_xor_sync(FULLMASK, ay, 1);
        s2[c] = pack2(ax, ay);
        float kx, ky; unpack2(K[0][c], kx, ky);
        p02[c] = pack2(__shfl_sync(FULLMASK, kx, mate_src),
                       __shfl_sync(FULLMASK, ky, mate_src));
    }
    float osA[4], osP[4];
    #pragma unroll
    for (int j = 0; j < 4; j++) {
        u64 c2 = C2p[j * 4 + 0][tid];
        u64 aA = mul2u(s2[0], c2);
        u64 aP = mul2u(p02[0], c2);
        #pragma unroll
        for (int c = 1; c < 4; c++) {
            c2 = C2p[j * 4 + c][tid];
            aA = fma2u(s2[c],  c2, aA);
            aP = fma2u(p02[c], c2, aP);
        }
        float x, y;
        unpack2(aA, x, y); osA[j] = x + y;
        unpack2(aP, x, y); osP[j] = x + y;
    }
    u64 oA0 = pack2(osA[0], osA[1]), oA1 = pack2(osA[2], osA[3]);
    u64 oP0 = pack2(osP[0], osP[1]), oP1 = pack2(osP[2], osP[3]);
    u64 mA0 = pack2(__shfl_xor_sync(FULLMASK, osA[0], 1), __shfl_xor_sync(FULLMASK, osA[1], 1));
    u64 mA1 = pack2(__shfl_xor_sync(FULLMASK, osA[2], 1), __shfl_xor_sync(FULLMASK, osA[3], 1));
    u64 mP0 = pack2(__shfl_xor_sync(FULLMASK, osP[0], 1), __shfl_xor_sync(FULLMASK, osP[1], 1));
    u64 mP1 = pack2(__shfl_xor_sync(FULLMASK, osP[2], 1), __shfl_xor_sync(FULLMASK, osP[3], 1));
    bool li = (l != 0);
    pA0f[0] = li ? mA0 : oA0; pA0f[1] = li ? mA1 : oA1;
    pA0f[2] = li ? oA0 : mA0; pA0f[3] = li ? oA1 : mA1;
    pArf[0] = li ? mP0 : oP0; pArf[1] = li ? mP1 : oP1;
    pArf[2] = li ? oP0 : mP0; pArf[3] = li ? oP1 : mP1;
}

// ---------------- Kernel B: FGW, 2 lanes per (node,template) ----------------
__global__ void __launch_bounds__(64, 8)
otgnn_fgw_kernel(const int* __restrict__ dst,
                 const float* __restrict__ Wm,
                 const float* __restrict__ bvec,
                 float* __restrict__ out)
{
    __shared__ u64 eMh_s[36][64];  // ex2(Mhn), thread-private slots
    __shared__ u64 C2p[16][64];    // EKC-scaled C2 own rows, thread-private
    __shared__ int   idxs[2][17];
    __shared__ float xn2s[2][17];
    __shared__ float fgw_s[2][16];

    const int tid  = threadIdx.x;
    const int w    = tid >> 5;
    const int lane = tid & 31;
    const int node = blockIdx.x * 2 + w;
    const int t    = lane >> 1;
    const int l    = lane & 1;
    const int mate_src = lane & ~1;
    const bool l0 = (l == 0);

    if (lane < 17) {
        int id = lane ? __ldg(&dst[node * 16 + lane - 1]) : node;
        idxs[w][lane] = id;
        xn2s[w][lane] = g_xn2[id];
    }
    __syncwarp();

    const float EKC = 7.21347520444482f;   // 5 * log2(e)
    const float HF  = -0.5f * EKC;
    const u64 ONE   = pack2(1.f, 1.f);
    const u64 NEG1  = pack2(-1.f, -1.f);
    const u64 EIGHTH = pack2(0.125f, 0.125f);

    // Own C2 rows 4l..4l+3; cc2; scale by EKC; stash in smem
    float cc2v[8];
    {
        float c2r[4][8];
        #pragma unroll
        for (int j = 0; j < 4; j++) {
            const float4* p = (const float4*)&g_C2s[(t * 8 + 4 * l + j) * 8];
            float4 a = __ldg(&p[0]), b = __ldg(&p[1]);
            c2r[j][0]=a.x; c2r[j][1]=a.y; c2r[j][2]=a.z; c2r[j][3]=a.w;
            c2r[j][4]=b.x; c2r[j][5]=b.y; c2r[j][6]=b.z; c2r[j][7]=b.w;
        }
        #pragma unroll
        for (int c = 0; c < 8; c++) {
            float a = c2r[0][c]*c2r[0][c] + c2r[1][c]*c2r[1][c]
                    + c2r[2][c]*c2r[2][c] + c2r[3][c]*c2r[3][c];
            a += __shfl_xor_sync(FULLMASK, a, 1);
            cc2v[c] = a * 0.125f;
        }
        #pragma unroll
        for (int j = 0; j < 4; j++)
            #pragma unroll
            for (int c = 0; c < 4; c++)
                C2p[j * 4 + c][tid] = pack2(c2r[j][2*c] * EKC, c2r[j][2*c+1] * EKC);

        // eMh = ex2(Mhn), Mhn = -(M + c1h + cc2) * 0.5 * EKC
        float tf2c[8];
        float4 ta = *(const float4*)&g_tf2[t * 8];
        float4 tb = *(const float4*)&g_tf2[t * 8 + 4];
        tf2c[0]=ta.x; tf2c[1]=ta.y; tf2c[2]=ta.z; tf2c[3]=ta.w;
        tf2c[4]=tb.x; tf2c[5]=tb.y; tf2c[6]=tb.z; tf2c[7]=tb.w;
        #pragma unroll
        for (int r = 0; r < 9; r++) {
            int row = (r < 8) ? 2 * r + l : 16;   // lane1 r=8 duplicates row16 (x0 later)
            int id = idxs[w][row];
            float n2 = xn2s[w][row];
            float4 g0 = __ldg((const float4*)&g_G[id * 128 + t * 8]);
            float4 g1 = __ldg((const float4*)&g_G[id * 128 + t * 8 + 4]);
            float gg[8] = {g0.x,g0.y,g0.z,g0.w,g1.x,g1.y,g1.z,g1.w};
            float c1h = (r == 0 && l0) ? (16.f / 17.f) : (1.f / 17.f);
            #pragma unroll
            for (int c = 0; c < 4; c++) {
                float mx = (n2 + tf2c[2*c]   - 2.f * gg[2*c])   * (1.f / 128.f);
                float my = (n2 + tf2c[2*c+1] - 2.f * gg[2*c+1]) * (1.f / 128.f);
                eMh_s[r * 4 + c][tid] = pack2(ex2((mx + c1h + cc2v[2*c])   * HF),
                                              ex2((my + c1h + cc2v[2*c+1]) * HF));
            }
        }
    }

    // State (all u64-packed)
    u64 K[9][4], vr[4], u2[9];
    #pragma unroll
    for (int r = 0; r < 9; r++) {
        float init = (r == 8) ? (l0 ? 1.f / 136.f : 0.f) : (1.f / 136.f);
        u64 iv = pack2(init, init);
        #pragma unroll
        for (int c = 0; c < 4; c++) K[r][c] = iv;
        u2[r] = ONE;
    }
    #pragma unroll
    for (int c = 0; c < 4; c++) vr[c] = ONE;

    #pragma unroll 1
    for (int outer = 0; outer < 5; outer++) {
        // P in place: K <- u * K * v
        #pragma unroll
        for (int r = 0; r < 9; r++) {
            #pragma unroll
            for (int c = 0; c < 4; c++)
                K[r][c] = mul2u(mul2u(K[r][c], vr[c]), u2[r]);
        }
        u64 pA0f[4], pArf[4];
        compute_pA(K, C2p, tid, l, mate_src, pA0f, pArf);

        // K <- P * eMh * (row0 ratio); column scale absorbed into v-init.
        #pragma unroll
        for (int c = 0; c < 4; c++) {
            float prx, pry; unpack2(pArf[c], prx, pry);
            u64 epr = pack2(ex2(prx), ex2(pry));
            u64 dd = fma2u(pArf[c], NEG1, pA0f[c]);   // pA0 - pAr
            float ddx, ddy; unpack2(dd, ddx, ddy);
            u64 rfx = l0 ? pack2(ex2(ddx), ex2(ddy)) : ONE;
            K[0][c] = mul2u(mul2u(K[0][c], eMh_s[c][tid]), rfx);
            #pragma unroll
            for (int r = 1; r < 9; r++)
                K[r][c] = mul2u(K[r][c], eMh_s[r * 4 + c][tid]);
            vr[c] = epr;
        }

        // Sinkhorn (raw reciprocals; constants telescope to 1/8 fold below)
        #pragma unroll 1
        for (int inner = 0; inner < 10; inner++) {
            #pragma unroll
            for (int r = 0; r < 9; r++) {
                u64 da = mul2u(K[r][0], vr[0]);
                u64 db = mul2u(K[r][1], vr[1]);
                da = fma2u(K[r][2], vr[2], da);
                db = fma2u(K[r][3], vr[3], db);
                da = add2u(da, db);
                float dx, dy; unpack2(da, dx, dy);
                float uu = rcpf(dx + dy + 1e-30f);
                u2[r] = pack2(uu, uu);
            }
            #pragma unroll
            for (int c = 0; c < 4; c++) {
                u64 pa = mul2u(K[0][c], u2[0]);
                u64 pb = mul2u(K[1][c], u2[1]);
                pa = fma2u(K[2][c], u2[2], pa);
                pb = fma2u(K[3][c], u2[3], pb);
                pa = fma2u(K[4][c], u2[4], pa);
                pb = fma2u(K[5][c], u2[5], pb);
                pa = fma2u(K[6][c], u2[6], pa);
                pb = fma2u(K[7][c], u2[7], pb);
                pa = fma2u(K[8][c], u2[8], pa);
                pa = add2u(pa, pb);
                float px, py; unpack2(pa, px, py);
                px += __shfl_xor_sync(FULLMASK, px, 1);
                py += __shfl_xor_sync(FULLMASK, py, 1);
                vr[c] = pack2(rcpf(px + 1e-30f), rcpf(py + 1e-30f));
            }
        }
        #pragma unroll
        for (int r = 0; r < 9; r++) u2[r] = mul2u(u2[r], EIGHTH);
    }

    // ---- Final: P in place, recompute Mhn, fgw = -(1/EKC) sum((Mhn+pA).*P) ----
    #pragma unroll
    for (int r = 0; r < 9; r++) {
        #pragma unroll
        for (int c = 0; c < 4; c++)
            K[r][c] = mul2u(mul2u(K[r][c], vr[c]), u2[r]);
    }
    {
        u64 pA0f[4], pArf[4];
        compute_pA(K, C2p, tid, l, mate_src, pA0f, pArf);

        float tf2c[8];
        float4 ta = *(const float4*)&g_tf2[t * 8];
        float4 tb = *(const float4*)&g_tf2[t * 8 + 4];
        tf2c[0]=ta.x; tf2c[1]=ta.y; tf2c[2]=ta.z; tf2c[3]=ta.w;
        tf2c[4]=tb.x; tf2c[5]=tb.y; tf2c[6]=tb.z; tf2c[7]=tb.w;

        u64 accv = 0ull;
        #pragma unroll
        for (int r = 0; r < 9; r++) {
            int row = (r < 8) ? 2 * r + l : 16;
            int id = idxs[w][row];
            float n2 = xn2s[w][row];
            float4 g0 = __ldg((const float4*)&g_G[id * 128 + t * 8]);
            float4 g1 = __ldg((const float4*)&g_G[id * 128 + t * 8 + 4]);
            float gg[8] = {g0.x,g0.y,g0.z,g0.w,g1.x,g1.y,g1.z,g1.w};
            float c1h = (r == 0 && l0) ? (16.f / 17.f) : (1.f / 17.f);
            const u64* pa = (r == 0 && l0) ? pA0f : pArf;
            #pragma unroll
            for (int c = 0; c < 4; c++) {
                float mx = (n2 + tf2c[2*c]   - 2.f * gg[2*c])   * (1.f / 128.f);
                float my = (n2 + tf2c[2*c+1] - 2.f * gg[2*c+1]) * (1.f / 128.f);
                float pax, pay; unpack2(pa[c], pax, pay);
                u64 g = pack2((mx + c1h + cc2v[2*c])   * HF + pax,
                              (my + c1h + cc2v[2*c+1]) * HF + pay);
                accv = fma2u(g, K[r][c], accv);
            }
        }
        float ax, ay; unpack2(accv, ax, ay);
        float loc = ax + ay;
        loc += __shfl_xor_sync(FULLMASK, loc, 1);
        if (l0) fgw_s[w][t] = loc * (-1.f / EKC);
    }
    __syncwarp();

    if (lane < 8) {
        float o = __ldg(&bvec[lane]);
        #pragma unroll
        for (int tt = 0; tt < 16; tt++)
            o += fgw_s[w][tt] * __ldg(&Wm[tt * 8 + lane]);
        out[node * 8 + lane] = o;
    }
}

extern "C" void kernel_launch(void* const* d_in, const int* in_sizes, int n_in,
                              void* d_out, int out_size) {
    const float* x   = (const float*)d_in[0];
    const int*   ei  = (const int*)d_in[1];
    const float* lt  = (const float*)d_in[2];
    const float* tf  = (const float*)d_in[3];
    const float* Wm  = (const float*)d_in[4];
    const float* bv  = (const float*)d_in[5];
    float* out = (float*)d_out;

    const int N = in_sizes[0] / 128;   // 10000 (even)
    const int* dst = ei + N * 16;

    precompute_kernel<<<(N + 31) / 32, 128>>>(x, lt, tf, N);
    otgnn_fgw_kernel<<<N / 2, 64>>>(dst, Wm, bv, out);
}